// round 17
// baseline (speedup 1.0000x reference)
#include <cuda_runtime.h>
#include <cuda_fp16.h>
#include <cstdint>

// ---------------- problem constants ----------------
#define L_SEQ    1024
#define D_MODEL  1024
#define D_INNER  2048
#define N_STATE  16
#define DT_RANK  64
#define X_DBL_W  96   // DT_RANK + 2*N_STATE
#define CHUNK    32
#define NCHUNK   (L_SEQ / CHUNK)   // 32
#define KSPLIT_X 8                 // xdbl_conv K-split

// ---------------- fp32 scratch ----------------
__device__ float g_xr[L_SEQ * 2 * D_INNER];      // x_and_res [1024,4096]
__device__ float g_xconv[L_SEQ * D_INNER];       // [1024,2048]
__device__ float g_xdbl[L_SEQ * X_DBL_W];        // [1024,96]
__device__ float g_xdp[KSPLIT_X * L_SEQ * X_DBL_W]; // xdbl K-split partials
__device__ float g_tmp[3 * 1024 * 1024];         // GEMM2 split-K partials

// ---------------- chunked-scan scratch ----------------
__device__ float g_P[NCHUNK * D_INNER * N_STATE];
__device__ float g_S[NCHUNK * D_INNER * N_STATE];
__device__ float g_h0[NCHUNK * D_INNER * N_STATE];

// ---------------- fp16 split scratch ----------------
// A = [Ah | Al] (M x 2K) row-major; B = [Bh ; Bl] (2K x N) K-major
__device__ __half g_aext[1024 * 4096];           // x split, then ysc split
__device__ __half g_b1e[2048 * 4096];            // W_in split  [2*1024, 4096]
__device__ __half g_b2e[4096 * 1024];            // W_out split [2*2048, 1024]

// =====================================================================
// base-PTX helpers (compute_103-safe)
// =====================================================================
__device__ __forceinline__ uint32_t smem_u32(const void* p) {
    uint32_t a;
    asm("{ .reg .u64 t; cvta.to.shared.u64 t, %1; cvt.u32.u64 %0, t; }" : "=r"(a) : "l"(p));
    return a;
}
__device__ __forceinline__ void cp16(uint32_t s, const void* g) {
    asm volatile("cp.async.cg.shared.global [%0], [%1], 16;" :: "r"(s), "l"(g));
}
#define CP_COMMIT() asm volatile("cp.async.commit_group;" ::: "memory")

#define LDSM_X4(r0, r1, r2, r3, addr) \
    asm volatile("ldmatrix.sync.aligned.m8n8.x4.shared.b16 {%0,%1,%2,%3}, [%4];" \
        : "=r"(r0), "=r"(r1), "=r"(r2), "=r"(r3) : "r"(addr))
#define LDSM_X2_T(r0, r1, addr) \
    asm volatile("ldmatrix.sync.aligned.m8n8.x2.trans.shared.b16 {%0,%1}, [%2];" \
        : "=r"(r0), "=r"(r1) : "r"(addr))
#define MMA16816(d, a, b) \
    asm volatile("mma.sync.aligned.m16n8k16.row.col.f32.f16.f16.f32 " \
        "{%0,%1,%2,%3}, {%4,%5,%6,%7}, {%8,%9}, {%0,%1,%2,%3};" \
        : "+f"((d)[0]), "+f"((d)[1]), "+f"((d)[2]), "+f"((d)[3]) \
        : "r"((a)[0]), "r"((a)[1]), "r"((a)[2]), "r"((a)[3]), "r"((b)[0]), "r"((b)[1]))

// =====================================================================
// HMMA GEMM over extended K (3 split-terms folded into K)
// tile 128x128x64, 8 warps, 3-stage cp.async pipeline.
// =====================================================================
#define GBM 128
#define GBN 128
#define A_STR 144
#define B_STR 272
#define A_BYTES (128 * A_STR)
#define B_BYTES (64 * B_STR)
#define STAGE_B (A_BYTES + B_BYTES)
#define NSTAGE 3
#define GSMEM (NSTAGE * STAGE_B)

__global__ void __launch_bounds__(256, 2) gemm_mma(
    const __half* __restrict__ A, const __half* __restrict__ B,
    float* __restrict__ C0, float* __restrict__ C1,
    float* __restrict__ C2, float* __restrict__ C3,
    int N, int Kext, int korig, int lda, int ldb) {
    extern __shared__ __align__(16) char smem[];
    const uint32_t sbase = smem_u32(smem);
    const int tid = threadIdx.x;
    const int lane = tid & 31, wid = tid >> 5;
    const int m0 = blockIdx.y * GBM, n0 = blockIdx.x * GBN;
    const int z = blockIdx.z;
    const int Kz = Kext / gridDim.z;
    const int ke0 = z * Kz;
    float* C = (z == 0) ? C0 : (z == 1) ? C1 : (z == 2) ? C2 : C3;

    const __half* Ag = A + (size_t)m0 * lda;
    const __half* Bg = B + n0;

    const int wm = (wid & 1) * 64;
    const int wn = (wid >> 1) * 32;

    float acc[4][4][4];
#pragma unroll
    for (int i = 0; i < 4; ++i)
#pragma unroll
        for (int j = 0; j < 4; ++j)
#pragma unroll
            for (int q = 0; q < 4; ++q) acc[i][j][q] = 0.f;

    const int nIter = Kz >> 6;

    auto load_tile = [&](int it, int stage) {
        int kt = ke0 + (it << 6);
        int kA = (kt < korig) ? kt : kt - korig;
        int kB = (kt < 2 * korig) ? kt : kt - 2 * korig;
        uint32_t sA = sbase + stage * STAGE_B;
        uint32_t sB = sA + A_BYTES;
#pragma unroll
        for (int c = tid; c < 2048; c += 256) {
            if (c < 1024) {
                int r = c >> 3, col = (c & 7) * 16;
                cp16(sA + r * A_STR + col,
                     (const char*)(Ag + (size_t)r * lda + kA) + col);
            } else {
                int cc = c - 1024;
                int r = cc >> 4, col = (cc & 15) * 16;
                cp16(sB + r * B_STR + col,
                     (const char*)(Bg + (size_t)(kB + r) * ldb) + col);
            }
        }
    };

    load_tile(0, 0);
    CP_COMMIT();
    load_tile(1, 1);
    CP_COMMIT();

    const uint32_t aOff = (wm + (lane & 15)) * A_STR + (lane >> 4) * 16;
    const uint32_t bOff = (lane & 15) * B_STR + wn * 2;

    int cs = 0, ls = 2;
    for (int it = 0; it < nIter; ++it) {
        asm volatile("cp.async.wait_group 1;" ::: "memory");
        __syncthreads();

        if (it + 2 < nIter) load_tile(it + 2, ls);
        CP_COMMIT();

        uint32_t sA = sbase + cs * STAGE_B + aOff;
        uint32_t sB = sbase + cs * STAGE_B + A_BYTES + bOff;
#pragma unroll
        for (int ks = 0; ks < 4; ++ks) {
            uint32_t a[4][4], b[4][2];
#pragma unroll
            for (int mt = 0; mt < 4; ++mt)
                LDSM_X4(a[mt][0], a[mt][1], a[mt][2], a[mt][3],
                        sA + mt * (16 * A_STR) + ks * 32);
#pragma unroll
            for (int nt = 0; nt < 4; ++nt)
                LDSM_X2_T(b[nt][0], b[nt][1], sB + ks * (16 * B_STR) + nt * 16);
#pragma unroll
            for (int mt = 0; mt < 4; ++mt)
#pragma unroll
                for (int nt = 0; nt < 4; ++nt)
                    MMA16816(acc[mt][nt], a[mt], b[nt]);
        }
        cs = (cs == 2) ? 0 : cs + 1;
        ls = (ls == 2) ? 0 : ls + 1;
    }

    const int qr = lane >> 2, qc = (lane & 3) * 2;
#pragma unroll
    for (int mt = 0; mt < 4; ++mt) {
        int row = m0 + wm + mt * 16 + qr;
#pragma unroll
        for (int nt = 0; nt < 4; ++nt) {
            int col = n0 + wn + nt * 8 + qc;
            *(float2*)(C + (size_t)row * N + col) =
                make_float2(acc[mt][nt][0], acc[mt][nt][1]);
            *(float2*)(C + (size_t)(row + 8) * N + col) =
                make_float2(acc[mt][nt][2], acc[mt][nt][3]);
        }
    }
}

// out += t0 + t1 + t2   (GEMM2 split-K reduction)
__global__ void add4_kernel(float* __restrict__ out) {
    int i = (blockIdx.x * 256 + threadIdx.x) * 4;
    float4 a = *(const float4*)(out + i);
    float4 b = *(const float4*)(g_tmp + i);
    float4 c = *(const float4*)(g_tmp + 1024 * 1024 + i);
    float4 d = *(const float4*)(g_tmp + 2 * 1024 * 1024 + i);
    a.x += b.x + c.x + d.x; a.y += b.y + c.y + d.y;
    a.z += b.z + c.z + d.z; a.w += b.w + c.w + d.w;
    *(float4*)(out + i) = a;
}

// =====================================================================
// merged conversion kernel (one launch)
// =====================================================================
__device__ __forceinline__ void split2(float2 v, __half2& hh, __half2& ll) {
    __half h0 = __float2half(v.x), h1 = __float2half(v.y);
    hh.x = h0; hh.y = h1;
    ll.x = __float2half(v.x - __half2float(h0));
    ll.y = __float2half(v.y - __half2float(h1));
}

__global__ void cvt_all(const float* __restrict__ x,
                        const float* __restrict__ W_in,
                        const float* __restrict__ W_out) {
    int b = blockIdx.x;
    if (b < 2048) {
        int i2 = (b * 256 + threadIdx.x) * 2;
        const int C = 1024;
        int r = i2 >> 10, c = i2 & 1023;
        __half2 hh, ll;
        split2(*(const float2*)(x + i2), hh, ll);
        __half* row = g_aext + (size_t)r * 2 * C;
        *(__half2*)(row + c) = hh;
        *(__half2*)(row + C + c) = ll;
    } else if (b < 10240) {
        int i2 = ((b - 2048) * 256 + threadIdx.x) * 2;
        const int KN = 1024 * 4096;
        __half2 hh, ll;
        split2(*(const float2*)(W_in + i2), hh, ll);
        *(__half2*)(g_b1e + i2) = hh;
        *(__half2*)(g_b1e + KN + i2) = ll;
    } else {
        int i2 = ((b - 10240) * 256 + threadIdx.x) * 2;
        const int KN = 2048 * 1024;
        __half2 hh, ll;
        split2(*(const float2*)(W_out + i2), hh, ll);
        *(__half2*)(g_b2e + i2) = hh;
        *(__half2*)(g_b2e + KN + i2) = ll;
    }
}

// =====================================================================
// fused: causal depthwise conv (K=4) + SiLU + x_dbl partial GEMM
// grid (L_SEQ/8, 8): 8 t-rows, k-slice of 256 per block
// =====================================================================
__global__ void xdbl_conv(const float* __restrict__ Wx,
                          const float* __restrict__ conv_w,
                          const float* __restrict__ conv_b) {
    __shared__ float xs[8][256];
    int t0 = blockIdx.x * 8;
    int ks = blockIdx.y;                               // 0..7
    int n = threadIdx.x;                               // 0..95
    int k0 = ks * 256;

    for (int i = n; i < 8 * 256; i += 96) {
        int tt = i >> 8, kk = i & 255;
        int t = t0 + tt, d = k0 + kk;
        float4 w = *(const float4*)(conv_w + d * 4);
        float s = conv_b[d];
        if (t >= 3) s += g_xr[(size_t)(t - 3) * 4096 + d] * w.x;
        if (t >= 2) s += g_xr[(size_t)(t - 2) * 4096 + d] * w.y;
        if (t >= 1) s += g_xr[(size_t)(t - 1) * 4096 + d] * w.z;
        s += g_xr[(size_t)t * 4096 + d] * w.w;
        float v = __fdividef(s, 1.f + __expf(-s));
        xs[tt][kk] = v;
        g_xconv[(size_t)t * D_INNER + d] = v;
    }
    __syncthreads();

    float acc[8];
#pragma unroll
    for (int tt = 0; tt < 8; ++tt) acc[tt] = 0.f;
#pragma unroll 8
    for (int kk = 0; kk < 256; ++kk) {
        float w = Wx[(size_t)(k0 + kk) * X_DBL_W + n];
#pragma unroll
        for (int tt = 0; tt < 8; ++tt) acc[tt] = fmaf(xs[tt][kk], w, acc[tt]);
    }
#pragma unroll
    for (int tt = 0; tt < 8; ++tt)
        g_xdp[((size_t)ks * L_SEQ + t0 + tt) * X_DBL_W + n] = acc[tt];
}

__global__ void xdbl_reduce() {
    int i = blockIdx.x * 256 + threadIdx.x;            // < 98304
    const int S = L_SEQ * X_DBL_W;
    float s = 0.f;
#pragma unroll
    for (int k = 0; k < KSPLIT_X; ++k) s += g_xdp[(size_t)k * S + i];
    g_xdbl[i] = s;
}

// =====================================================================
// chunked selective scan, delta fused (recomputed from x_dbl + W_dt).
// one thread per channel d; chunk rows staged in smem.
//   sx[t][0:64] = dt,  sx[t][64:80] = B,  sx[t][80:96] = C
// =====================================================================
__device__ __forceinline__ void stage_chunk(float (*sx)[X_DBL_W], int tbase, int tid) {
    const float* src = g_xdbl + (size_t)tbase * X_DBL_W;
    float* dst = &sx[0][0];
    for (int i = tid; i < CHUNK * X_DBL_W; i += 256)
        dst[i] = src[i];
}

// compute per-thread delta for the chunk: k-outer streaming of W_dt col d
__device__ __forceinline__ void chunk_delta(float* dl, const float (*sx)[X_DBL_W],
                                            const float* Wdt, const float* bdt, int d) {
    float bb = bdt[d];
#pragma unroll
    for (int t = 0; t < CHUNK; ++t) dl[t] = bb;
#pragma unroll 4
    for (int k = 0; k < DT_RANK; ++k) {
        float w = Wdt[(size_t)k * D_INNER + d];
#pragma unroll
        for (int t = 0; t < CHUNK; ++t) dl[t] = fmaf(sx[t][k], w, dl[t]);
    }
#pragma unroll
    for (int t = 0; t < CHUNK; ++t) {
        float a = dl[t];
        dl[t] = (a > 20.f) ? a : log1pf(__expf(a));
    }
}

__global__ void scan_p1(const float* __restrict__ A_log,
                        const float* __restrict__ Wdt,
                        const float* __restrict__ bdt) {
    __shared__ float sx[CHUNK][X_DBL_W];
    int d = blockIdx.x * 256 + threadIdx.x;            // 0..2047
    int c = blockIdx.y;
    int tbase = c * CHUNK;

    stage_chunk(sx, tbase, threadIdx.x);
    __syncthreads();

    float dl[CHUNK];
    chunk_delta(dl, sx, Wdt, bdt, d);

    float Av[N_STATE], P[N_STATE], S[N_STATE];
#pragma unroll
    for (int n = 0; n < N_STATE; ++n) {
        Av[n] = -__expf(A_log[d * N_STATE + n]);
        P[n] = 1.f;
        S[n] = 0.f;
    }
    for (int i = 0; i < CHUNK; ++i) {
        float u = g_xconv[(size_t)(tbase + i) * D_INNER + d];
        float bu = dl[i] * u;
#pragma unroll
        for (int n = 0; n < N_STATE; ++n) {
            float dA = __expf(dl[i] * Av[n]);
            S[n] = fmaf(dA, S[n], bu * sx[i][DT_RANK + n]);
            P[n] *= dA;
        }
    }
    float* Pd = g_P + ((size_t)c * D_INNER + d) * N_STATE;
    float* Sd = g_S + ((size_t)c * D_INNER + d) * N_STATE;
#pragma unroll
    for (int n = 0; n < N_STATE; n += 4) {
        *(float4*)(Pd + n) = make_float4(P[n], P[n + 1], P[n + 2], P[n + 3]);
        *(float4*)(Sd + n) = make_float4(S[n], S[n + 1], S[n + 2], S[n + 3]);
    }
}

__global__ void scan_p2() {
    int dn = blockIdx.x * 256 + threadIdx.x;
    float h = 0.f;
#pragma unroll
    for (int c = 0; c < NCHUNK; ++c) {
        int idx = c * (D_INNER * N_STATE) + dn;
        g_h0[idx] = h;
        h = fmaf(g_P[idx], h, g_S[idx]);
    }
}

__global__ void scan_p3(const float* __restrict__ A_log,
                        const float* __restrict__ Dp,
                        const float* __restrict__ Wdt,
                        const float* __restrict__ bdt) {
    __shared__ float sx[CHUNK][X_DBL_W];
    int d = blockIdx.x * 256 + threadIdx.x;            // 0..2047
    int c = blockIdx.y;
    int tbase = c * CHUNK;

    stage_chunk(sx, tbase, threadIdx.x);
    __syncthreads();

    float dl[CHUNK];
    chunk_delta(dl, sx, Wdt, bdt, d);

    float Av[N_STATE], h[N_STATE];
    const float* h0 = g_h0 + ((size_t)c * D_INNER + d) * N_STATE;
#pragma unroll
    for (int n = 0; n < N_STATE; ++n) {
        Av[n] = -__expf(A_log[d * N_STATE + n]);
        h[n] = h0[n];
    }
    float Dd = Dp[d];
    for (int i = 0; i < CHUNK; ++i) {
        int t = tbase + i;
        float u = g_xconv[(size_t)t * D_INNER + d];
        float bu = dl[i] * u;
        float y = 0.f;
#pragma unroll
        for (int n = 0; n < N_STATE; ++n) {
            float dA = __expf(dl[i] * Av[n]);
            h[n] = fmaf(dA, h[n], bu * sx[i][DT_RANK + n]);
            y = fmaf(h[n], sx[i][DT_RANK + N_STATE + n], y);
        }
        float r = g_xr[(size_t)t * 4096 + D_INNER + d];
        float sr = __fdividef(r, 1.f + __expf(-r));
        float val = (y + u * Dd) * sr;
        __half hh = __float2half(val);
        __half ll = __float2half(val - __half2float(hh));
        g_aext[(size_t)t * 4096 + d] = hh;                 // Ah
        g_aext[(size_t)t * 4096 + D_INNER + d] = ll;       // Al
    }
}

// =====================================================================
// launch
// =====================================================================
template <typename T>
static T* sym_addr(const void* sym) {
    void* p = nullptr;
    cudaGetSymbolAddress(&p, sym);
    return (T*)p;
}

extern "C" void kernel_launch(void* const* d_in, const int* in_sizes, int n_in,
                              void* d_out, int out_size) {
    const float* x      = (const float*)d_in[0];
    const float* W_in   = (const float*)d_in[1];
    const float* conv_w = (const float*)d_in[2];
    const float* conv_b = (const float*)d_in[3];
    const float* W_x    = (const float*)d_in[4];
    const float* W_dt   = (const float*)d_in[5];
    const float* b_dt   = (const float*)d_in[6];
    const float* A_log  = (const float*)d_in[7];
    const float* Dvec   = (const float*)d_in[8];
    const float* W_out  = (const float*)d_in[9];
    float* out = (float*)d_out;

    cudaFuncSetAttribute(gemm_mma, cudaFuncAttributeMaxDynamicSharedMemorySize, GSMEM);

    float* xr   = sym_addr<float>(g_xr);
    float* tmp  = sym_addr<float>(g_tmp);
    __half* ae  = sym_addr<__half>(g_aext);
    __half* b1e = sym_addr<__half>(g_b1e);
    __half* b2e = sym_addr<__half>(g_b2e);

    // 0) all fp32->fp16 split conversions in one launch
    cvt_all<<<14336, 256>>>(x, W_in, W_out);

    // 1) x_and_res = x @ W_in   [1024,4096]; Kext=3072, korig=1024
    gemm_mma<<<dim3(4096 / GBN, 1024 / GBM, 1), 256, GSMEM>>>(
        ae, b1e, xr, nullptr, nullptr, nullptr, 4096, 3072, 1024, 2048, 4096);

    // 2+3) fused conv+silu+x_dbl (K-split x8) + reduce
    xdbl_conv<<<dim3(L_SEQ / 8, KSPLIT_X), X_DBL_W>>>(W_x, conv_w, conv_b);
    xdbl_reduce<<<L_SEQ * X_DBL_W / 256, 256>>>();

    // 4+5) chunked selective scan with delta fused; p3 emits fp16-split ysc
    scan_p1<<<dim3(D_INNER / 256, NCHUNK), 256>>>(A_log, W_dt, b_dt);
    scan_p2<<<D_INNER * N_STATE / 256, 256>>>();
    scan_p3<<<dim3(D_INNER / 256, NCHUNK), 256>>>(A_log, Dvec, W_dt, b_dt);

    // 6) out = ysc @ W_out  [1024,1024]; Kext=6144, korig=2048, split-K z=4
    gemm_mma<<<dim3(1024 / GBN, 1024 / GBM, 4), 256, GSMEM>>>(
        ae, b2e, out, tmp, tmp + 1024 * 1024, tmp + 2 * 1024 * 1024,
        1024, 6144, 2048, 4096, 1024);
    add4_kernel<<<1024 * 1024 / 1024, 256>>>(out);
}